// round 4
// baseline (speedup 1.0000x reference)
#include <cuda_runtime.h>

#define H 256
#define NA 100000
#define NB 250000
#define NM 2000
#define AF 133
#define BF 147
#define MAXNB 6
#define AH (AF + H)   // 389

typedef unsigned long long ull;
typedef long long ll;

// Scratch (device globals: allocation-guard-safe)
__device__ float g_inp[(ll)NB * H];     // 256 MB
__device__ float g_msg0[(ll)NB * H];    // 256 MB
__device__ float g_msg1[(ll)NB * H];    // 256 MB
__device__ float g_amsg[(ll)NA * H];    // 102 MB
__device__ float g_molsum[NM * H];
__device__ float g_wsum[NM];

// ---------------- packed f32x2 helpers (FFMA2 path, sm_103a) ----------------
__device__ __forceinline__ ull pack2(float lo, float hi) {
    ull r; asm("mov.b64 %0, {%1,%2};" : "=l"(r) : "f"(lo), "f"(hi)); return r;
}
__device__ __forceinline__ float2 unpack2(ull v) {
    float2 f; asm("mov.b64 {%0,%1}, %2;" : "=f"(f.x), "=f"(f.y) : "l"(v)); return f;
}
__device__ __forceinline__ void ffma2(ull& d, ull a, ull b) {
    asm("fma.rn.f32x2 %0, %1, %2, %0;" : "+l"(d) : "l"(a), "l"(b));
}

// ---------------- fused GEMM ----------------
struct GArgs {
    const float* A;        // mode0: f_bonds
    const float* W;        // weight [K x 256] row-major
    const int*   b2a;      // mode1
    const int*   b2revb;   // mode1
    const float* amsg;     // mode1/2
    const float* msgcur;   // mode1
    const float* inp;      // mode1 epilogue
    const float* fatoms;   // mode2
    const float* b_o;      // mode2
    const float* w_atoms;  // mode2
    const int*   mol_ids;  // mode2
    float* out0;           // mode0: inp store; mode2: molsum (atomics)
    float* out1;           // mode0: relu msg; mode1: msg_next
    int M, K;
};

template <int MODE>
__global__ __launch_bounds__(256) void gemm_kernel(GArgs g) {
    __shared__ float As[16][132];   // padded: 132*4=528B row, 16B-aligned
    __shared__ float Bs[16][128];

    const int tid  = threadIdx.x;
    const int bm   = blockIdx.x * 128;
    const int bn   = blockIdx.y * 128;
    const int trow = (tid >> 4) * 8;
    const int tcol = (tid & 15) * 8;

    ull acc[8][4];
#pragma unroll
    for (int i = 0; i < 8; i++)
#pragma unroll
        for (int j = 0; j < 4; j++) acc[i][j] = 0ull;

    // A-tile loader geometry: thread covers row m, 8 consecutive k
    const int  m      = tid >> 1;
    const int  kk     = (tid & 1) * 8;
    const int  growl  = bm + m;
    const bool rvalid = growl < g.M;

    const float* ap1 = nullptr;
    const float* ap2 = nullptr;
    if (MODE == 1 && rvalid) {
        ap1 = g.amsg   + (ll)g.b2a[growl]   * H;
        ap2 = g.msgcur + (ll)g.b2revb[growl] * H;
    }

    const int KT = (g.K + 15) / 16;
    for (int kt = 0; kt < KT; kt++) {
        const int k0 = kt * 16;

        // ---- load A tile ----
        if (MODE == 1) {
            if (rvalid) {
                float4 x0 = *(const float4*)(ap1 + k0 + kk);
                float4 x1 = *(const float4*)(ap1 + k0 + kk + 4);
                float4 y0 = *(const float4*)(ap2 + k0 + kk);
                float4 y1 = *(const float4*)(ap2 + k0 + kk + 4);
                As[kk + 0][m] = x0.x - y0.x; As[kk + 1][m] = x0.y - y0.y;
                As[kk + 2][m] = x0.z - y0.z; As[kk + 3][m] = x0.w - y0.w;
                As[kk + 4][m] = x1.x - y1.x; As[kk + 5][m] = x1.y - y1.y;
                As[kk + 6][m] = x1.z - y1.z; As[kk + 7][m] = x1.w - y1.w;
            } else {
#pragma unroll
                for (int i = 0; i < 8; i++) As[kk + i][m] = 0.f;
            }
        } else {
#pragma unroll
            for (int i = 0; i < 8; i++) {
                int gk = k0 + kk + i;
                float v = 0.f;
                if (rvalid && gk < g.K) {
                    if (MODE == 0) v = g.A[(ll)growl * BF + gk];
                    else v = (gk < AF) ? g.fatoms[(ll)growl * AF + gk]
                                       : g.amsg[(ll)growl * H + (gk - AF)];
                }
                As[kk + i][m] = v;
            }
        }
        // ---- load B tile (coalesced) ----
#pragma unroll
        for (int i = 0; i < 8; i++) {
            int e = tid + i * 256;
            int k = e >> 7, n = e & 127;
            int gk = k0 + k;
            Bs[k][n] = (gk < g.K) ? g.W[(ll)gk * H + bn + n] : 0.f;
        }
        __syncthreads();

        // ---- 8x8 micro-tile with packed f32x2 FMA ----
#pragma unroll
        for (int k = 0; k < 16; k++) {
            float4 a0 = *(const float4*)&As[k][trow];
            float4 a1 = *(const float4*)&As[k][trow + 4];
            float4 b0 = *(const float4*)&Bs[k][tcol];
            float4 b1 = *(const float4*)&Bs[k][tcol + 4];
            ull bp0 = pack2(b0.x, b0.y), bp1 = pack2(b0.z, b0.w);
            ull bp2 = pack2(b1.x, b1.y), bp3 = pack2(b1.z, b1.w);
            float av[8] = {a0.x, a0.y, a0.z, a0.w, a1.x, a1.y, a1.z, a1.w};
#pragma unroll
            for (int i = 0; i < 8; i++) {
                ull ap = pack2(av[i], av[i]);
                ffma2(acc[i][0], ap, bp0);
                ffma2(acc[i][1], ap, bp1);
                ffma2(acc[i][2], ap, bp2);
                ffma2(acc[i][3], ap, bp3);
            }
        }
        __syncthreads();
    }

    // ---- epilogue ----
    const int gcol = bn + tcol;
    if (MODE == 2) {
        float bo[8];
#pragma unroll
        for (int j = 0; j < 8; j++) bo[j] = g.b_o[gcol + j];
        int   cur_mol = -1;
        float accv[8];
#pragma unroll
        for (int j = 0; j < 8; j++) accv[j] = 0.f;
#pragma unroll
        for (int i = 0; i < 8; i++) {
            int grow = bm + trow + i;
            if (grow < g.M) {
                int   mol = g.mol_ids[grow];
                float w   = g.w_atoms[grow];
                if (mol != cur_mol) {
                    if (cur_mol >= 0) {
#pragma unroll
                        for (int j = 0; j < 8; j++)
                            atomicAdd(&g.out0[(ll)cur_mol * H + gcol + j], accv[j]);
                    }
                    cur_mol = mol;
#pragma unroll
                    for (int j = 0; j < 8; j++) accv[j] = 0.f;
                }
#pragma unroll
                for (int j = 0; j < 4; j++) {
                    float2 u = unpack2(acc[i][j]);
                    accv[2 * j]     += fmaxf(u.x + bo[2 * j], 0.f) * w;
                    accv[2 * j + 1] += fmaxf(u.y + bo[2 * j + 1], 0.f) * w;
                }
            }
        }
        if (cur_mol >= 0) {
#pragma unroll
            for (int j = 0; j < 8; j++)
                atomicAdd(&g.out0[(ll)cur_mol * H + gcol + j], accv[j]);
        }
    } else {
#pragma unroll
        for (int i = 0; i < 8; i++) {
            int grow = bm + trow + i;
            if (grow >= g.M) continue;
            float v[8];
#pragma unroll
            for (int j = 0; j < 4; j++) {
                float2 u = unpack2(acc[i][j]);
                v[2 * j] = u.x; v[2 * j + 1] = u.y;
            }
            ll off = (ll)grow * H + gcol;
            if (MODE == 0) {
                *(float4*)&g.out0[off]     = make_float4(v[0], v[1], v[2], v[3]);
                *(float4*)&g.out0[off + 4] = make_float4(v[4], v[5], v[6], v[7]);
                *(float4*)&g.out1[off]     = make_float4(fmaxf(v[0], 0.f), fmaxf(v[1], 0.f),
                                                         fmaxf(v[2], 0.f), fmaxf(v[3], 0.f));
                *(float4*)&g.out1[off + 4] = make_float4(fmaxf(v[4], 0.f), fmaxf(v[5], 0.f),
                                                         fmaxf(v[6], 0.f), fmaxf(v[7], 0.f));
            } else {  // MODE 1
                float4 i0 = *(const float4*)&g.inp[off];
                float4 i1 = *(const float4*)&g.inp[off + 4];
                *(float4*)&g.out1[off]     = make_float4(fmaxf(v[0] + i0.x, 0.f), fmaxf(v[1] + i0.y, 0.f),
                                                         fmaxf(v[2] + i0.z, 0.f), fmaxf(v[3] + i0.w, 0.f));
                *(float4*)&g.out1[off + 4] = make_float4(fmaxf(v[4] + i1.x, 0.f), fmaxf(v[5] + i1.y, 0.f),
                                                         fmaxf(v[6] + i1.z, 0.f), fmaxf(v[7] + i1.w, 0.f));
            }
        }
    }
}

// ---------------- per-atom weighted neighbor-message gather ----------------
__global__ __launch_bounds__(256) void gather_kernel(const float* __restrict__ msg,
                                                     const float* __restrict__ w_bonds,
                                                     const int* __restrict__ a2b,
                                                     float* __restrict__ amsg) {
    int tid  = threadIdx.x;
    int a    = blockIdx.x * 4 + (tid >> 6);  // 4 atoms/block, 64 threads each
    int lane = tid & 63;
    float4 s = make_float4(0.f, 0.f, 0.f, 0.f);
#pragma unroll
    for (int j = 0; j < MAXNB; j++) {
        int   b = a2b[a * MAXNB + j];
        float w = w_bonds[b];
        float4 mv = *(const float4*)&msg[(ll)b * H + lane * 4];
        s.x += w * mv.x; s.y += w * mv.y; s.z += w * mv.z; s.w += w * mv.w;
    }
    *(float4*)&amsg[(ll)a * H + lane * 4] = s;
}

__global__ void zero_kernel(float* molsum, float* wsum) {
    int i = blockIdx.x * 256 + threadIdx.x;
    if (i < NM * H) molsum[i] = 0.f;
    if (i < NM) wsum[i] = 0.f;
}

__global__ void wsum_kernel(const float* __restrict__ w_atoms,
                            const int* __restrict__ mol_ids,
                            float* __restrict__ wsum) {
    int i = blockIdx.x * 256 + threadIdx.x;
    if (i < NA) atomicAdd(&wsum[mol_ids[i]], w_atoms[i]);
}

__global__ void finalize_kernel(const float* __restrict__ molsum,
                                const float* __restrict__ wsum,
                                const float* __restrict__ deg,
                                float* __restrict__ out) {
    int m = blockIdx.x, hc = threadIdx.x;
    float w = wsum[m];
    float v = (w > 0.f) ? molsum[m * H + hc] / w : 0.f;
    out[m * H + hc] = deg[m] * v;
}

extern "C" void kernel_launch(void* const* d_in, const int* in_sizes, int n_in,
                              void* d_out, int out_size) {
    const float* f_atoms = (const float*)d_in[0];
    const float* f_bonds = (const float*)d_in[1];
    const float* w_atoms = (const float*)d_in[2];
    const float* w_bonds = (const float*)d_in[3];
    const float* W_i     = (const float*)d_in[4];
    const float* W_h     = (const float*)d_in[5];
    const float* W_o     = (const float*)d_in[6];
    const float* b_o     = (const float*)d_in[7];
    const float* deg     = (const float*)d_in[8];
    const int*   a2b     = (const int*)d_in[9];
    const int*   b2a     = (const int*)d_in[10];
    const int*   b2revb  = (const int*)d_in[11];
    const int*   mol_ids = (const int*)d_in[12];

    float *p_inp, *p_msg0, *p_msg1, *p_amsg, *p_molsum, *p_wsum;
    cudaGetSymbolAddress((void**)&p_inp, g_inp);
    cudaGetSymbolAddress((void**)&p_msg0, g_msg0);
    cudaGetSymbolAddress((void**)&p_msg1, g_msg1);
    cudaGetSymbolAddress((void**)&p_amsg, g_amsg);
    cudaGetSymbolAddress((void**)&p_molsum, g_molsum);
    cudaGetSymbolAddress((void**)&p_wsum, g_wsum);

    zero_kernel<<<NM, 256>>>(p_molsum, p_wsum);

    dim3 gb((NB + 127) / 128, 2);
    dim3 ga((NA + 127) / 128, 2);

    // input layer: inp = f_bonds @ W_i ; msg0 = relu(inp)
    GArgs g0 = {};
    g0.A = f_bonds; g0.W = W_i; g0.out0 = p_inp; g0.out1 = p_msg0;
    g0.M = NB; g0.K = BF;
    gemm_kernel<0><<<gb, 256>>>(g0);

    // depth iter 1
    gather_kernel<<<NA / 4, 256>>>(p_msg0, w_bonds, a2b, p_amsg);
    GArgs g1 = {};
    g1.W = W_h; g1.b2a = b2a; g1.b2revb = b2revb;
    g1.amsg = p_amsg; g1.msgcur = p_msg0; g1.inp = p_inp; g1.out1 = p_msg1;
    g1.M = NB; g1.K = H;
    gemm_kernel<1><<<gb, 256>>>(g1);

    // depth iter 2
    gather_kernel<<<NA / 4, 256>>>(p_msg1, w_bonds, a2b, p_amsg);
    GArgs g2 = g1;
    g2.msgcur = p_msg1; g2.out1 = p_msg0;
    gemm_kernel<1><<<gb, 256>>>(g2);

    // readout gather
    gather_kernel<<<NA / 4, 256>>>(p_msg0, w_bonds, a2b, p_amsg);

    wsum_kernel<<<(NA + 255) / 256, 256>>>(w_atoms, mol_ids, p_wsum);

    // atom readout GEMM + fused segment-sum
    GArgs g3 = {};
    g3.fatoms = f_atoms; g3.amsg = p_amsg; g3.W = W_o; g3.b_o = b_o;
    g3.w_atoms = w_atoms; g3.mol_ids = mol_ids; g3.out0 = p_molsum;
    g3.M = NA; g3.K = AH;
    gemm_kernel<2><<<ga, 256>>>(g3);

    finalize_kernel<<<NM, 256>>>(p_molsum, p_wsum, deg, (float*)d_out);
}

// round 7
// speedup vs baseline: 1.0000x; 1.0000x over previous
#include <cuda_runtime.h>

#define H 256
#define NA 100000
#define NB 250000
#define NM 2000
#define AF 133
#define BF 147
#define MAXNB 6
#define AH (AF + H)   // 389

typedef unsigned long long ull;
typedef long long ll;

// Scratch (device globals: allocation-guard-safe)
__device__ float g_inp[(ll)NB * H];     // 256 MB
__device__ float g_msg0[(ll)NB * H];    // 256 MB
__device__ float g_msg1[(ll)NB * H];    // 256 MB
__device__ float g_amsg[(ll)NA * H];    // 102 MB
__device__ float g_molsum[NM * H];
__device__ float g_wsum[NM];

// ---------------- packed f32x2 helpers (FFMA2 path, sm_103a) ----------------
__device__ __forceinline__ ull pack2(float lo, float hi) {
    ull r; asm("mov.b64 %0, {%1,%2};" : "=l"(r) : "f"(lo), "f"(hi)); return r;
}
__device__ __forceinline__ float2 unpack2(ull v) {
    float2 f; asm("mov.b64 {%0,%1}, %2;" : "=f"(f.x), "=f"(f.y) : "l"(v)); return f;
}
__device__ __forceinline__ void ffma2(ull& d, ull a, ull b) {
    asm("fma.rn.f32x2 %0, %1, %2, %0;" : "+l"(d) : "l"(a), "l"(b));
}

// ---------------- fused GEMM ----------------
struct GArgs {
    const float* A;        // mode0: f_bonds
    const float* W;        // weight [K x 256] row-major
    const int*   b2a;      // mode1
    const int*   b2revb;   // mode1
    const float* amsg;     // mode1/2
    const float* msgcur;   // mode1
    const float* inp;      // mode1 epilogue
    const float* fatoms;   // mode2
    const float* b_o;      // mode2
    const float* w_atoms;  // mode2
    const int*   mol_ids;  // mode2
    float* out0;           // mode0: inp store; mode2: molsum (atomics)
    float* out1;           // mode0: relu msg; mode1: msg_next
    int M, K;
};

template <int MODE>
__global__ __launch_bounds__(256) void gemm_kernel(GArgs g) {
    __shared__ float As[16][132];   // padded: 132*4=528B row, 16B-aligned
    __shared__ float Bs[16][128];

    const int tid  = threadIdx.x;
    const int bm   = blockIdx.x * 128;
    const int bn   = blockIdx.y * 128;
    const int trow = (tid >> 4) * 8;
    const int tcol = (tid & 15) * 8;

    ull acc[8][4];
#pragma unroll
    for (int i = 0; i < 8; i++)
#pragma unroll
        for (int j = 0; j < 4; j++) acc[i][j] = 0ull;

    // A-tile loader geometry: thread covers row m, 8 consecutive k
    const int  m      = tid >> 1;
    const int  kk     = (tid & 1) * 8;
    const int  growl  = bm + m;
    const bool rvalid = growl < g.M;

    const float* ap1 = nullptr;
    const float* ap2 = nullptr;
    if (MODE == 1 && rvalid) {
        ap1 = g.amsg   + (ll)g.b2a[growl]   * H;
        ap2 = g.msgcur + (ll)g.b2revb[growl] * H;
    }

    const int KT = (g.K + 15) / 16;
    for (int kt = 0; kt < KT; kt++) {
        const int k0 = kt * 16;

        // ---- load A tile ----
        if (MODE == 1) {
            if (rvalid) {
                float4 x0 = *(const float4*)(ap1 + k0 + kk);
                float4 x1 = *(const float4*)(ap1 + k0 + kk + 4);
                float4 y0 = *(const float4*)(ap2 + k0 + kk);
                float4 y1 = *(const float4*)(ap2 + k0 + kk + 4);
                As[kk + 0][m] = x0.x - y0.x; As[kk + 1][m] = x0.y - y0.y;
                As[kk + 2][m] = x0.z - y0.z; As[kk + 3][m] = x0.w - y0.w;
                As[kk + 4][m] = x1.x - y1.x; As[kk + 5][m] = x1.y - y1.y;
                As[kk + 6][m] = x1.z - y1.z; As[kk + 7][m] = x1.w - y1.w;
            } else {
#pragma unroll
                for (int i = 0; i < 8; i++) As[kk + i][m] = 0.f;
            }
        } else {
#pragma unroll
            for (int i = 0; i < 8; i++) {
                int gk = k0 + kk + i;
                float v = 0.f;
                if (rvalid && gk < g.K) {
                    if (MODE == 0) v = g.A[(ll)growl * BF + gk];
                    else v = (gk < AF) ? g.fatoms[(ll)growl * AF + gk]
                                       : g.amsg[(ll)growl * H + (gk - AF)];
                }
                As[kk + i][m] = v;
            }
        }
        // ---- load B tile (coalesced) ----
#pragma unroll
        for (int i = 0; i < 8; i++) {
            int e = tid + i * 256;
            int k = e >> 7, n = e & 127;
            int gk = k0 + k;
            Bs[k][n] = (gk < g.K) ? g.W[(ll)gk * H + bn + n] : 0.f;
        }
        __syncthreads();

        // ---- 8x8 micro-tile with packed f32x2 FMA ----
#pragma unroll
        for (int k = 0; k < 16; k++) {
            float4 a0 = *(const float4*)&As[k][trow];
            float4 a1 = *(const float4*)&As[k][trow + 4];
            float4 b0 = *(const float4*)&Bs[k][tcol];
            float4 b1 = *(const float4*)&Bs[k][tcol + 4];
            ull bp0 = pack2(b0.x, b0.y), bp1 = pack2(b0.z, b0.w);
            ull bp2 = pack2(b1.x, b1.y), bp3 = pack2(b1.z, b1.w);
            float av[8] = {a0.x, a0.y, a0.z, a0.w, a1.x, a1.y, a1.z, a1.w};
#pragma unroll
            for (int i = 0; i < 8; i++) {
                ull ap = pack2(av[i], av[i]);
                ffma2(acc[i][0], ap, bp0);
                ffma2(acc[i][1], ap, bp1);
                ffma2(acc[i][2], ap, bp2);
                ffma2(acc[i][3], ap, bp3);
            }
        }
        __syncthreads();
    }

    // ---- epilogue ----
    const int gcol = bn + tcol;
    if (MODE == 2) {
        float bo[8];
#pragma unroll
        for (int j = 0; j < 8; j++) bo[j] = g.b_o[gcol + j];
        int   cur_mol = -1;
        float accv[8];
#pragma unroll
        for (int j = 0; j < 8; j++) accv[j] = 0.f;
#pragma unroll
        for (int i = 0; i < 8; i++) {
            int grow = bm + trow + i;
            if (grow < g.M) {
                int   mol = g.mol_ids[grow];
                float w   = g.w_atoms[grow];
                if (mol != cur_mol) {
                    if (cur_mol >= 0) {
#pragma unroll
                        for (int j = 0; j < 8; j++)
                            atomicAdd(&g.out0[(ll)cur_mol * H + gcol + j], accv[j]);
                    }
                    cur_mol = mol;
#pragma unroll
                    for (int j = 0; j < 8; j++) accv[j] = 0.f;
                }
#pragma unroll
                for (int j = 0; j < 4; j++) {
                    float2 u = unpack2(acc[i][j]);
                    accv[2 * j]     += fmaxf(u.x + bo[2 * j], 0.f) * w;
                    accv[2 * j + 1] += fmaxf(u.y + bo[2 * j + 1], 0.f) * w;
                }
            }
        }
        if (cur_mol >= 0) {
#pragma unroll
            for (int j = 0; j < 8; j++)
                atomicAdd(&g.out0[(ll)cur_mol * H + gcol + j], accv[j]);
        }
    } else {
#pragma unroll
        for (int i = 0; i < 8; i++) {
            int grow = bm + trow + i;
            if (grow >= g.M) continue;
            float v[8];
#pragma unroll
            for (int j = 0; j < 4; j++) {
                float2 u = unpack2(acc[i][j]);
                v[2 * j] = u.x; v[2 * j + 1] = u.y;
            }
            ll off = (ll)grow * H + gcol;
            if (MODE == 0) {
                *(float4*)&g.out0[off]     = make_float4(v[0], v[1], v[2], v[3]);
                *(float4*)&g.out0[off + 4] = make_float4(v[4], v[5], v[6], v[7]);
                *(float4*)&g.out1[off]     = make_float4(fmaxf(v[0], 0.f), fmaxf(v[1], 0.f),
                                                         fmaxf(v[2], 0.f), fmaxf(v[3], 0.f));
                *(float4*)&g.out1[off + 4] = make_float4(fmaxf(v[4], 0.f), fmaxf(v[5], 0.f),
                                                         fmaxf(v[6], 0.f), fmaxf(v[7], 0.f));
            } else {  // MODE 1
                float4 i0 = *(const float4*)&g.inp[off];
                float4 i1 = *(const float4*)&g.inp[off + 4];
                *(float4*)&g.out1[off]     = make_float4(fmaxf(v[0] + i0.x, 0.f), fmaxf(v[1] + i0.y, 0.f),
                                                         fmaxf(v[2] + i0.z, 0.f), fmaxf(v[3] + i0.w, 0.f));
                *(float4*)&g.out1[off + 4] = make_float4(fmaxf(v[4] + i1.x, 0.f), fmaxf(v[5] + i1.y, 0.f),
                                                         fmaxf(v[6] + i1.z, 0.f), fmaxf(v[7] + i1.w, 0.f));
            }
        }
    }
}

// ---------------- per-atom weighted neighbor-message gather ----------------
__global__ __launch_bounds__(256) void gather_kernel(const float* __restrict__ msg,
                                                     const float* __restrict__ w_bonds,
                                                     const int* __restrict__ a2b,
                                                     float* __restrict__ amsg) {
    int tid  = threadIdx.x;
    int a    = blockIdx.x * 4 + (tid >> 6);  // 4 atoms/block, 64 threads each
    int lane = tid & 63;
    float4 s = make_float4(0.f, 0.f, 0.f, 0.f);
#pragma unroll
    for (int j = 0; j < MAXNB; j++) {
        int   b = a2b[a * MAXNB + j];
        float w = w_bonds[b];
        float4 mv = *(const float4*)&msg[(ll)b * H + lane * 4];
        s.x += w * mv.x; s.y += w * mv.y; s.z += w * mv.z; s.w += w * mv.w;
    }
    *(float4*)&amsg[(ll)a * H + lane * 4] = s;
}

__global__ void zero_kernel(float* molsum, float* wsum) {
    int i = blockIdx.x * 256 + threadIdx.x;
    if (i < NM * H) molsum[i] = 0.f;
    if (i < NM) wsum[i] = 0.f;
}

__global__ void wsum_kernel(const float* __restrict__ w_atoms,
                            const int* __restrict__ mol_ids,
                            float* __restrict__ wsum) {
    int i = blockIdx.x * 256 + threadIdx.x;
    if (i < NA) atomicAdd(&wsum[mol_ids[i]], w_atoms[i]);
}

__global__ void finalize_kernel(const float* __restrict__ molsum,
                                const float* __restrict__ wsum,
                                const float* __restrict__ deg,
                                float* __restrict__ out) {
    int m = blockIdx.x, hc = threadIdx.x;
    float w = wsum[m];
    float v = (w > 0.f) ? molsum[m * H + hc] / w : 0.f;
    out[m * H + hc] = deg[m] * v;
}

extern "C" void kernel_launch(void* const* d_in, const int* in_sizes, int n_in,
                              void* d_out, int out_size) {
    const float* f_atoms = (const float*)d_in[0];
    const float* f_bonds = (const float*)d_in[1];
    const float* w_atoms = (const float*)d_in[2];
    const float* w_bonds = (const float*)d_in[3];
    const float* W_i     = (const float*)d_in[4];
    const float* W_h     = (const float*)d_in[5];
    const float* W_o     = (const float*)d_in[6];
    const float* b_o     = (const float*)d_in[7];
    const float* deg     = (const float*)d_in[8];
    const int*   a2b     = (const int*)d_in[9];
    const int*   b2a     = (const int*)d_in[10];
    const int*   b2revb  = (const int*)d_in[11];
    const int*   mol_ids = (const int*)d_in[12];

    float *p_inp, *p_msg0, *p_msg1, *p_amsg, *p_molsum, *p_wsum;
    cudaGetSymbolAddress((void**)&p_inp, g_inp);
    cudaGetSymbolAddress((void**)&p_msg0, g_msg0);
    cudaGetSymbolAddress((void**)&p_msg1, g_msg1);
    cudaGetSymbolAddress((void**)&p_amsg, g_amsg);
    cudaGetSymbolAddress((void**)&p_molsum, g_molsum);
    cudaGetSymbolAddress((void**)&p_wsum, g_wsum);

    zero_kernel<<<NM, 256>>>(p_molsum, p_wsum);

    dim3 gb((NB + 127) / 128, 2);
    dim3 ga((NA + 127) / 128, 2);

    // input layer: inp = f_bonds @ W_i ; msg0 = relu(inp)
    GArgs g0 = {};
    g0.A = f_bonds; g0.W = W_i; g0.out0 = p_inp; g0.out1 = p_msg0;
    g0.M = NB; g0.K = BF;
    gemm_kernel<0><<<gb, 256>>>(g0);

    // depth iter 1
    gather_kernel<<<NA / 4, 256>>>(p_msg0, w_bonds, a2b, p_amsg);
    GArgs g1 = {};
    g1.W = W_h; g1.b2a = b2a; g1.b2revb = b2revb;
    g1.amsg = p_amsg; g1.msgcur = p_msg0; g1.inp = p_inp; g1.out1 = p_msg1;
    g1.M = NB; g1.K = H;
    gemm_kernel<1><<<gb, 256>>>(g1);

    // depth iter 2
    gather_kernel<<<NA / 4, 256>>>(p_msg1, w_bonds, a2b, p_amsg);
    GArgs g2 = g1;
    g2.msgcur = p_msg1; g2.out1 = p_msg0;
    gemm_kernel<1><<<gb, 256>>>(g2);

    // readout gather
    gather_kernel<<<NA / 4, 256>>>(p_msg0, w_bonds, a2b, p_amsg);

    wsum_kernel<<<(NA + 255) / 256, 256>>>(w_atoms, mol_ids, p_wsum);

    // atom readout GEMM + fused segment-sum
    GArgs g3 = {};
    g3.fatoms = f_atoms; g3.amsg = p_amsg; g3.W = W_o; g3.b_o = b_o;
    g3.w_atoms = w_atoms; g3.mol_ids = mol_ids; g3.out0 = p_molsum;
    g3.M = NA; g3.K = AH;
    gemm_kernel<2><<<ga, 256>>>(g3);

    finalize_kernel<<<NM, 256>>>(p_molsum, p_wsum, deg, (float*)d_out);
}

// round 9
// speedup vs baseline: 1.4523x; 1.4522x over previous
#include <cuda_runtime.h>
#include <cuda_bf16.h>
#include <cstdint>

#define H 256
#define NA 100000
#define NB 250000
#define NM 2000
#define AF 133
#define BF 147
#define MAXNB 6

#define MT_B 1954          // ceil(250000/128)
#define MT_A 782           // ceil(100000/128)
#define KP0 192
#define KP1 256
#define KP2 448

typedef long long ll;
typedef unsigned int uint;
typedef unsigned short ushort;
typedef unsigned long long ull;

// ---------------- device scratch (allocation-guard-safe) ----------------
__device__ float  g_inp[(ll)NB * H];
__device__ float  g_msg0[(ll)NB * H];
__device__ float  g_msg1[(ll)NB * H];   // also reused as atom_hidden scratch
__device__ float  g_amsg[(ll)NA * H];
__device__ ushort g_wi_hi[256 * KP0], g_wi_lo[256 * KP0];
__device__ ushort g_wh_hi[256 * KP1], g_wh_lo[256 * KP1];
__device__ ushort g_wo_hi[256 * KP2], g_wo_lo[256 * KP2];
__device__ float  g_molsum[NM * H];
__device__ float  g_wsum[NM];

// ---------------- helpers ----------------
__device__ __forceinline__ uint smem_u32(const void* p) {
    uint a;
    asm("{ .reg .u64 t; cvta.to.shared.u64 t, %1; cvt.u32.u64 %0, t; }" : "=r"(a) : "l"(p));
    return a;
}
// bf16 split: hi = truncate, lo = rn(v - hi)
__device__ __forceinline__ uint hi_pair(float a, float b) {
    uint r;
    asm("prmt.b32 %0, %1, %2, 0x7632;" : "=r"(r)
        : "r"(__float_as_uint(a)), "r"(__float_as_uint(b)));
    return r;
}
__device__ __forceinline__ uint lo_pair(float a, float b) {
    float la = a - __uint_as_float(__float_as_uint(a) & 0xFFFF0000u);
    float lb = b - __uint_as_float(__float_as_uint(b) & 0xFFFF0000u);
    __nv_bfloat162 t = __floats2bfloat162_rn(la, lb);
    return *(uint*)&t;
}
__device__ __forceinline__ void ldsm4(uint* r, uint addr) {
    asm volatile("ldmatrix.sync.aligned.m8n8.x4.shared.b16 {%0,%1,%2,%3}, [%4];"
                 : "=r"(r[0]), "=r"(r[1]), "=r"(r[2]), "=r"(r[3]) : "r"(addr));
}
__device__ __forceinline__ void mma16816(float* d, const uint* a, const uint* b) {
    asm volatile(
        "mma.sync.aligned.m16n8k16.row.col.f32.bf16.bf16.f32 "
        "{%0,%1,%2,%3}, {%4,%5,%6,%7}, {%8,%9}, {%0,%1,%2,%3};"
        : "+f"(d[0]), "+f"(d[1]), "+f"(d[2]), "+f"(d[3])
        : "r"(a[0]), "r"(a[1]), "r"(a[2]), "r"(a[3]), "r"(b[0]), "r"(b[1]));
}

// ---------------- SMEM plan: 4 planes of 128 rows x 40 bf16 (padded, 80B stride)
#define PLN 5120                 // ushorts per plane
#define PLNB 10240               // bytes per plane

struct TArgs {
    const float* A;                      // mode0: f_bonds
    const ushort *w_hi, *w_lo;           // pre-split weights [256 x KPAD], k-contig
    const float *amsg, *msgc;            // mode1 gather sources / mode2 amsg
    const int *b2a, *b2revb;
    const float* inp;                    // mode1 epilogue add
    const float* fatoms;                 // mode2
    float *inp_out, *msg_out;            // outputs (mode2: msg_out = hidden scratch)
    const float *b_o, *w_atoms;          // mode2
    int M;
};

template <int MODE>
__global__ __launch_bounds__(256, 1) void hgemm(TArgs g) {
    constexpr int KPAD = (MODE == 0) ? KP0 : ((MODE == 1) ? KP1 : KP2);
    constexpr int KT   = KPAD / 32;
    constexpr int KSRC = (MODE == 0) ? BF : ((MODE == 1) ? H : (AF + H));

    __shared__ __align__(16) ushort sm[4 * PLN];
    const uint sbase = smem_u32(sm);

    const int tid = threadIdx.x;
    const int lane = tid & 31, wid = tid >> 5;
    const int wr = wid >> 1, wc = wid & 1;           // warp 32-row block / 64-col block
    const int bm = blockIdx.x * 128;
    const int bn = blockIdx.y * 128;

    // ---- loader geometry: thread -> (local row row2, k-half) ----
    const int row2 = tid >> 1, half = tid & 1;
    const int growl = bm + row2;
    const bool rv = growl < g.M;
    const float *p1 = nullptr, *p2 = nullptr;
    if (MODE == 1 && rv) {
        p1 = g.amsg + (ll)g.b2a[growl] * H;
        p2 = g.msgc + (ll)g.b2revb[growl] * H;
    }
    const ushort* wg_hi = g.w_hi + (ll)(bn + row2) * KPAD;
    const ushort* wg_lo = g.w_lo + (ll)(bn + row2) * KPAD;

    // ---- ldmatrix per-lane addresses (constant across chunks) ----
    const int a_row = (lane & 7) + ((lane >> 3) & 1) * 8;
    const int a_k   = (lane >> 4) * 8;
    const uint addrA = sbase + ((uint)((wr * 32 + a_row) * 40 + a_k) << 1);
    const int b_n = (lane & 7) + (lane >> 4) * 8;
    const int b_k = ((lane >> 3) & 1) * 8;
    const uint addrB = sbase + 2 * PLNB + ((uint)((wc * 64 + b_n) * 40 + b_k) << 1);

    float acc[2][8][4];
#pragma unroll
    for (int mi = 0; mi < 2; mi++)
#pragma unroll
        for (int ni = 0; ni < 8; ni++)
#pragma unroll
            for (int q = 0; q < 4; q++) acc[mi][ni][q] = 0.f;

    // ---- prefetch registers ----
    float pv[16];
    uint4 pbh[2], pbl[2];

    auto prefetch = [&](int c) {
        const int kbase = c * 32 + half * 16;
        if (MODE == 1) {
#pragma unroll
            for (int i = 0; i < 4; i++) {
                float4 x = rv ? *(const float4*)(p1 + kbase + i * 4) : make_float4(0, 0, 0, 0);
                float4 y = rv ? *(const float4*)(p2 + kbase + i * 4) : make_float4(0, 0, 0, 0);
                pv[4 * i + 0] = x.x - y.x; pv[4 * i + 1] = x.y - y.y;
                pv[4 * i + 2] = x.z - y.z; pv[4 * i + 3] = x.w - y.w;
            }
        } else {
#pragma unroll
            for (int t = 0; t < 16; t++) {
                int k = kbase + t;
                float v = 0.f;
                if (rv && k < KSRC) {
                    if (MODE == 0) v = __ldg(&g.A[(ll)growl * BF + k]);
                    else v = (k < AF) ? __ldg(&g.fatoms[(ll)growl * AF + k])
                                      : __ldg(&g.amsg[(ll)growl * H + (k - AF)]);
                }
                pv[t] = v;
            }
        }
#pragma unroll
        for (int i = 0; i < 2; i++) {
            pbh[i] = *(const uint4*)(wg_hi + kbase + i * 8);
            pbl[i] = *(const uint4*)(wg_lo + kbase + i * 8);
        }
    };

    prefetch(0);

    for (int c = 0; c < KT; c++) {
        if (c) __syncthreads();            // prev compute done before overwrite
        // ---- STS: A split planes ----
        {
            uint ao = (uint)(row2 * 40 + half * 16);
#pragma unroll
            for (int i = 0; i < 4; i++) {
                uint2 hv = make_uint2(hi_pair(pv[4 * i], pv[4 * i + 1]),
                                      hi_pair(pv[4 * i + 2], pv[4 * i + 3]));
                uint2 lv = make_uint2(lo_pair(pv[4 * i], pv[4 * i + 1]),
                                      lo_pair(pv[4 * i + 2], pv[4 * i + 3]));
                *(uint2*)((char*)sm + ((ao + i * 4) << 1)) = hv;
                *(uint2*)((char*)sm + PLNB + ((ao + i * 4) << 1)) = lv;
            }
            // B planes (plain copies of pre-split weights)
#pragma unroll
            for (int i = 0; i < 2; i++) {
                *(uint4*)((char*)sm + 2 * PLNB + ((ao + i * 8) << 1)) = pbh[i];
                *(uint4*)((char*)sm + 3 * PLNB + ((ao + i * 8) << 1)) = pbl[i];
            }
        }
        __syncthreads();
        if (c + 1 < KT) prefetch(c + 1);   // LDGs overlap with MMA compute

        // ---- compute: 2 x k16 sub-steps ----
#pragma unroll
        for (int ks = 0; ks < 2; ks++) {
            const uint kb2 = (uint)(ks * 32);        // bytes
            uint Ah[2][4], Al[2][4], Bh[4][4], Bl[4][4];
#pragma unroll
            for (int mi = 0; mi < 2; mi++) {
                ldsm4(Ah[mi], addrA + kb2 + mi * 1280);
                ldsm4(Al[mi], addrA + PLNB + kb2 + mi * 1280);
            }
#pragma unroll
            for (int nt = 0; nt < 4; nt++) {
                ldsm4(Bh[nt], addrB + kb2 + nt * 1280);
                ldsm4(Bl[nt], addrB + PLNB + kb2 + nt * 1280);
            }
#pragma unroll
            for (int mi = 0; mi < 2; mi++)
#pragma unroll
                for (int nt = 0; nt < 4; nt++)
#pragma unroll
                    for (int sub = 0; sub < 2; sub++) {
                        const int ni = nt * 2 + sub;
                        mma16816(acc[mi][ni], Ah[mi], &Bh[nt][sub * 2]);
                        mma16816(acc[mi][ni], Ah[mi], &Bl[nt][sub * 2]);
                        mma16816(acc[mi][ni], Al[mi], &Bh[nt][sub * 2]);
                    }
        }
    }

    // ---------------- epilogue ----------------
    const int grp = lane >> 2, qi = lane & 3;
#pragma unroll
    for (int mi = 0; mi < 2; mi++) {
        const int r0 = bm + wr * 32 + mi * 16 + grp;
        const int r1 = r0 + 8;
        float w0 = 0.f, w1 = 0.f;
        if (MODE == 2) {
            w0 = (r0 < g.M) ? __ldg(&g.w_atoms[r0]) : 0.f;
            w1 = (r1 < g.M) ? __ldg(&g.w_atoms[r1]) : 0.f;
        }
#pragma unroll
        for (int ni = 0; ni < 8; ni++) {
            const int col = bn + wc * 64 + ni * 8 + qi * 2;
            float c0 = acc[mi][ni][0], c1 = acc[mi][ni][1];
            float c2 = acc[mi][ni][2], c3 = acc[mi][ni][3];
            if (MODE == 0) {
                if (r0 < g.M) {
                    *(float2*)&g.inp_out[(ll)r0 * H + col] = make_float2(c0, c1);
                    *(float2*)&g.msg_out[(ll)r0 * H + col] =
                        make_float2(fmaxf(c0, 0.f), fmaxf(c1, 0.f));
                }
                if (r1 < g.M) {
                    *(float2*)&g.inp_out[(ll)r1 * H + col] = make_float2(c2, c3);
                    *(float2*)&g.msg_out[(ll)r1 * H + col] =
                        make_float2(fmaxf(c2, 0.f), fmaxf(c3, 0.f));
                }
            } else if (MODE == 1) {
                if (r0 < g.M) {
                    float2 iv = *(const float2*)&g.inp[(ll)r0 * H + col];
                    *(float2*)&g.msg_out[(ll)r0 * H + col] =
                        make_float2(fmaxf(c0 + iv.x, 0.f), fmaxf(c1 + iv.y, 0.f));
                }
                if (r1 < g.M) {
                    float2 iv = *(const float2*)&g.inp[(ll)r1 * H + col];
                    *(float2*)&g.msg_out[(ll)r1 * H + col] =
                        make_float2(fmaxf(c2 + iv.x, 0.f), fmaxf(c3 + iv.y, 0.f));
                }
            } else {
                float2 bo = *(const float2*)&g.b_o[col];
                if (r0 < g.M)
                    *(float2*)&g.msg_out[(ll)r0 * H + col] =
                        make_float2(fmaxf(c0 + bo.x, 0.f) * w0, fmaxf(c1 + bo.y, 0.f) * w0);
                if (r1 < g.M)
                    *(float2*)&g.msg_out[(ll)r1 * H + col] =
                        make_float2(fmaxf(c2 + bo.x, 0.f) * w1, fmaxf(c3 + bo.y, 0.f) * w1);
            }
        }
    }
}

// ---------------- weight prepack: [K x 256] fp32 -> [256 x Kpad] bf16 hi/lo ----
__global__ void prepack_w(const float* __restrict__ src, ushort* __restrict__ hi,
                          ushort* __restrict__ lo, int K, int Kpad) {
    int idx = blockIdx.x * 256 + threadIdx.x;
    if (idx >= 256 * Kpad) return;
    int n = idx / Kpad, k = idx - n * Kpad;
    float v = (k < K) ? src[(ll)k * 256 + n] : 0.f;
    uint u = __float_as_uint(v);
    hi[idx] = (ushort)(u >> 16);
    float lv = v - __uint_as_float(u & 0xFFFF0000u);
    __nv_bfloat16 b = __float2bfloat16(lv);
    lo[idx] = *(ushort*)&b;
}

// ---------------- small kernels ----------------
__global__ __launch_bounds__(256) void gather_kernel(const float* __restrict__ msg,
                                                     const float* __restrict__ w_bonds,
                                                     const int* __restrict__ a2b,
                                                     float* __restrict__ amsg) {
    int tid = threadIdx.x;
    int a = blockIdx.x * 4 + (tid >> 6);
    int lane = tid & 63;
    float4 s = make_float4(0.f, 0.f, 0.f, 0.f);
#pragma unroll
    for (int j = 0; j < MAXNB; j++) {
        int b = a2b[a * MAXNB + j];
        float w = w_bonds[b];
        float4 mv = *(const float4*)&msg[(ll)b * H + lane * 4];
        s.x += w * mv.x; s.y += w * mv.y; s.z += w * mv.z; s.w += w * mv.w;
    }
    *(float4*)&amsg[(ll)a * H + lane * 4] = s;
}

__global__ void zero_kernel(float* molsum, float* wsum) {
    int i = blockIdx.x * 256 + threadIdx.x;
    if (i < NM * H) molsum[i] = 0.f;
    if (i < NM) wsum[i] = 0.f;
}
__global__ void wsum_kernel(const float* __restrict__ w_atoms, const int* __restrict__ mol_ids,
                            float* __restrict__ wsum) {
    int i = blockIdx.x * 256 + threadIdx.x;
    if (i < NA) atomicAdd(&wsum[mol_ids[i]], w_atoms[i]);
}

// run-aggregated segment sum over sorted mol_ids (hid rows < NA valid)
__global__ __launch_bounds__(256) void segreduce_kernel(const float* __restrict__ hid,
                                                        const int* __restrict__ mol_ids,
                                                        float* __restrict__ molsum) {
    int col = blockIdx.y * 128 + (threadIdx.x & 127);
    int rbase = blockIdx.x * 128 + (threadIdx.x >> 7) * 64;
    if (rbase >= NA) return;
    int rend = rbase + 64; if (rend > NA) rend = NA;
    int cur = -1; float s = 0.f;
    for (int r = rbase; r < rend; r++) {
        int m = __ldg(&mol_ids[r]);
        float v = hid[(ll)r * H + col];
        if (m != cur) {
            if (cur >= 0) atomicAdd(&molsum[(ll)cur * H + col], s);
            cur = m; s = 0.f;
        }
        s += v;
    }
    if (cur >= 0) atomicAdd(&molsum[(ll)cur * H + col], s);
}

__global__ void finalize_kernel(const float* __restrict__ molsum, const float* __restrict__ wsum,
                                const float* __restrict__ deg, float* __restrict__ out) {
    int m = blockIdx.x, hc = threadIdx.x;
    float w = wsum[m];
    float v = (w > 0.f) ? molsum[m * H + hc] / w : 0.f;
    out[m * H + hc] = deg[m] * v;
}

extern "C" void kernel_launch(void* const* d_in, const int* in_sizes, int n_in,
                              void* d_out, int out_size) {
    const float* f_atoms = (const float*)d_in[0];
    const float* f_bonds = (const float*)d_in[1];
    const float* w_atoms = (const float*)d_in[2];
    const float* w_bonds = (const float*)d_in[3];
    const float* W_i = (const float*)d_in[4];
    const float* W_h = (const float*)d_in[5];
    const float* W_o = (const float*)d_in[6];
    const float* b_o = (const float*)d_in[7];
    const float* deg = (const float*)d_in[8];
    const int* a2b = (const int*)d_in[9];
    const int* b2a = (const int*)d_in[10];
    const int* b2revb = (const int*)d_in[11];
    const int* mol_ids = (const int*)d_in[12];

    float *p_inp, *p_msg0, *p_msg1, *p_amsg, *p_molsum, *p_wsum;
    ushort *p_wih, *p_wil, *p_whh, *p_whl, *p_woh, *p_wol;
    cudaGetSymbolAddress((void**)&p_inp, g_inp);
    cudaGetSymbolAddress((void**)&p_msg0, g_msg0);
    cudaGetSymbolAddress((void**)&p_msg1, g_msg1);
    cudaGetSymbolAddress((void**)&p_amsg, g_amsg);
    cudaGetSymbolAddress((void**)&p_molsum, g_molsum);
    cudaGetSymbolAddress((void**)&p_wsum, g_wsum);
    cudaGetSymbolAddress((void**)&p_wih, g_wi_hi);
    cudaGetSymbolAddress((void**)&p_wil, g_wi_lo);
    cudaGetSymbolAddress((void**)&p_whh, g_wh_hi);
    cudaGetSymbolAddress((void**)&p_whl, g_wh_lo);
    cudaGetSymbolAddress((void**)&p_woh, g_wo_hi);
    cudaGetSymbolAddress((void**)&p_wol, g_wo_lo);

    zero_kernel<<<NM, 256>>>(p_molsum, p_wsum);
    prepack_w<<<(256 * KP0 + 255) / 256, 256>>>(W_i, p_wih, p_wil, BF, KP0);
    prepack_w<<<(256 * KP1 + 255) / 256, 256>>>(W_h, p_whh, p_whl, H, KP1);
    prepack_w<<<(256 * KP2 + 255) / 256, 256>>>(W_o, p_woh, p_wol, AF + H, KP2);

    dim3 gb(MT_B, 2), ga(MT_A, 2);

    // input layer: inp = f_bonds @ W_i ; msg0 = relu(inp)
    TArgs g0 = {};
    g0.A = f_bonds; g0.w_hi = p_wih; g0.w_lo = p_wil;
    g0.inp_out = p_inp; g0.msg_out = p_msg0; g0.M = NB;
    hgemm<0><<<gb, 256>>>(g0);

    // depth iter 1
    gather_kernel<<<NA / 4, 256>>>(p_msg0, w_bonds, a2b, p_amsg);
    TArgs g1 = {};
    g1.w_hi = p_whh; g1.w_lo = p_whl; g1.amsg = p_amsg; g1.msgc = p_msg0;
    g1.b2a = b2a; g1.b2revb = b2revb; g1.inp = p_inp; g1.msg_out = p_msg1; g1.M = NB;
    hgemm<1><<<gb, 256>>>(g1);

    // depth iter 2
    gather_kernel<<<NA / 4, 256>>>(p_msg1, w_bonds, a2b, p_amsg);
    TArgs g2 = g1;
    g2.msgc = p_msg1; g2.msg_out = p_msg0;
    hgemm<1><<<gb, 256>>>(g2);

    // readout
    gather_kernel<<<NA / 4, 256>>>(p_msg0, w_bonds, a2b, p_amsg);
    wsum_kernel<<<(NA + 255) / 256, 256>>>(w_atoms, mol_ids, p_wsum);

    // atom readout GEMM -> hidden*w rows into g_msg1 scratch
    TArgs g3 = {};
    g3.fatoms = f_atoms; g3.amsg = p_amsg; g3.w_hi = p_woh; g3.w_lo = p_wol;
    g3.b_o = b_o; g3.w_atoms = w_atoms; g3.msg_out = p_msg1; g3.M = NA;
    hgemm<2><<<ga, 256>>>(g3);

    segreduce_kernel<<<dim3(MT_A, 2), 256>>>(p_msg1, mol_ids, p_molsum);
    finalize_kernel<<<NM, 256>>>(p_molsum, p_wsum, deg, (float*)d_out);
}

// round 10
// speedup vs baseline: 1.5092x; 1.0392x over previous
#include <cuda_runtime.h>
#include <cuda_bf16.h>
#include <cstdint>

#define H 256
#define NA 100000
#define NB 250000
#define NM 2000
#define AF 133
#define BF 147
#define MAXNB 6

#define MT_B 1954          // ceil(250000/128)
#define MT_A 782           // ceil(100000/128)
#define KP0 192
#define KP1 256
#define KP2 448

typedef long long ll;
typedef unsigned int uint;
typedef unsigned short ushort;
typedef unsigned long long ull;

// ---------------- device scratch (allocation-guard-safe) ----------------
__device__ float  g_inp[(ll)NB * H];
__device__ float  g_msg0[(ll)NB * H];   // iter2 output
__device__ float  g_msg1[(ll)NB * H];   // iter1 output / atom_hidden scratch
__device__ float  g_amsg[(ll)NA * H];
__device__ ushort g_wi_hi[256 * KP0], g_wi_lo[256 * KP0];
__device__ ushort g_wh_hi[256 * KP1], g_wh_lo[256 * KP1];
__device__ ushort g_wo_hi[256 * KP2], g_wo_lo[256 * KP2];
__device__ float  g_molsum[NM * H];
__device__ float  g_wsum[NM];

// ---------------- helpers ----------------
__device__ __forceinline__ uint smem_u32(const void* p) {
    uint a;
    asm("{ .reg .u64 t; cvta.to.shared.u64 t, %1; cvt.u32.u64 %0, t; }" : "=r"(a) : "l"(p));
    return a;
}
__device__ __forceinline__ uint hi_pair(float a, float b) {   // truncate-split hi
    uint r;
    asm("prmt.b32 %0, %1, %2, 0x7632;" : "=r"(r)
        : "r"(__float_as_uint(a)), "r"(__float_as_uint(b)));
    return r;
}
__device__ __forceinline__ uint lo_pair(float a, float b) {
    float la = a - __uint_as_float(__float_as_uint(a) & 0xFFFF0000u);
    float lb = b - __uint_as_float(__float_as_uint(b) & 0xFFFF0000u);
    __nv_bfloat162 t = __floats2bfloat162_rn(la, lb);
    return *(uint*)&t;
}
__device__ __forceinline__ void ldsm4(uint* r, uint addr) {
    asm volatile("ldmatrix.sync.aligned.m8n8.x4.shared.b16 {%0,%1,%2,%3}, [%4];"
                 : "=r"(r[0]), "=r"(r[1]), "=r"(r[2]), "=r"(r[3]) : "r"(addr));
}
__device__ __forceinline__ void mma16816(float* d, const uint* a, const uint* b) {
    asm volatile(
        "mma.sync.aligned.m16n8k16.row.col.f32.bf16.bf16.f32 "
        "{%0,%1,%2,%3}, {%4,%5,%6,%7}, {%8,%9}, {%0,%1,%2,%3};"
        : "+f"(d[0]), "+f"(d[1]), "+f"(d[2]), "+f"(d[3])
        : "r"(a[0]), "r"(a[1]), "r"(a[2]), "r"(a[3]), "r"(b[0]), "r"(b[1]));
}
__device__ __forceinline__ void cp16(uint dst, const void* src) {
    asm volatile("cp.async.ca.shared.global [%0], [%1], 16;" :: "r"(dst), "l"(src));
}
__device__ __forceinline__ void cp_commit() {
    asm volatile("cp.async.commit_group;" ::: "memory");
}
__device__ __forceinline__ void cp_wait0() {
    asm volatile("cp.async.wait_group 0;" ::: "memory");
}

// SMEM: 2 buffers x 4 planes x (128 rows x 40 bf16, 80B stride)
#define PLNB 10240
#define BUFB (4 * PLNB)          // 40960
#define SMEM_TOTAL (2 * BUFB)    // 81920

struct TArgs {
    const float* A;                      // mode0: f_bonds
    const ushort *w_hi, *w_lo;           // pre-split weights [256 x KPAD], k-contig
    const float *amsg, *msgc;            // mode1 gather sources / mode2 amsg
    const int *b2a, *b2revb;
    const float* inp;                    // mode1 epilogue add
    const float* fatoms;                 // mode2
    float *inp_out, *msg_out;            // outputs (mode2: msg_out = hidden scratch)
    const float *b_o, *w_atoms;          // mode2
    int M;
};

template <int MODE>
__global__ __launch_bounds__(256, 1) void hgemm(TArgs g) {
    constexpr int KPAD = (MODE == 0) ? KP0 : ((MODE == 1) ? KP1 : KP2);
    constexpr int KT   = KPAD / 32;
    constexpr int KSRC = (MODE == 0) ? BF : ((MODE == 1) ? H : (AF + H));

    extern __shared__ char smem[];
    const uint sb = smem_u32(smem);

    const int tid = threadIdx.x;
    const int lane = tid & 31, wid = tid >> 5;
    const int wr = wid >> 1, wc = wid & 1;
    const int bm = blockIdx.x * 128;
    const int bn = blockIdx.y * 128;

    // loader geometry: thread -> (row2, k-half)
    const int row2 = tid >> 1, half = tid & 1;
    const int growl = bm + row2;
    const bool rv = growl < g.M;
    const float *p1 = nullptr, *p2 = nullptr;
    if (MODE == 1 && rv) {
        p1 = g.amsg + (ll)g.b2a[growl] * H;
        p2 = g.msgc + (ll)g.b2revb[growl] * H;
    }
    const ushort* wg_hi = g.w_hi + (ll)(bn + row2) * KPAD;
    const ushort* wg_lo = g.w_lo + (ll)(bn + row2) * KPAD;

    // ldmatrix lane addresses (buffer-relative)
    const int a_row = (lane & 7) + ((lane >> 3) & 1) * 8;
    const int a_k   = (lane >> 4) * 8;
    const uint offA = ((uint)((wr * 32 + a_row) * 40 + a_k) << 1);
    const int b_n = (lane & 7) + (lane >> 4) * 8;
    const int b_k = ((lane >> 3) & 1) * 8;
    const uint offB = 2 * PLNB + ((uint)((wc * 64 + b_n) * 40 + b_k) << 1);

    float acc[2][8][4];
#pragma unroll
    for (int mi = 0; mi < 2; mi++)
#pragma unroll
        for (int ni = 0; ni < 8; ni++)
#pragma unroll
            for (int q = 0; q < 4; q++) acc[mi][ni][q] = 0.f;

    float pv[16];

    auto prefetchA = [&](int c) {
        const int kbase = c * 32 + half * 16;
        if (MODE == 1) {
#pragma unroll
            for (int i = 0; i < 4; i++) {
                float4 x = rv ? *(const float4*)(p1 + kbase + i * 4) : make_float4(0, 0, 0, 0);
                float4 y = rv ? *(const float4*)(p2 + kbase + i * 4) : make_float4(0, 0, 0, 0);
                // relu-on-read of reverse message (idempotent on iter-2 input)
                pv[4 * i + 0] = x.x - fmaxf(y.x, 0.f);
                pv[4 * i + 1] = x.y - fmaxf(y.y, 0.f);
                pv[4 * i + 2] = x.z - fmaxf(y.z, 0.f);
                pv[4 * i + 3] = x.w - fmaxf(y.w, 0.f);
            }
        } else {
#pragma unroll
            for (int t = 0; t < 16; t++) {
                int k = kbase + t;
                float v = 0.f;
                if (rv && k < KSRC) {
                    if (MODE == 0) v = __ldg(&g.A[(ll)growl * BF + k]);
                    else v = (k < AF) ? __ldg(&g.fatoms[(ll)growl * AF + k])
                                      : __ldg(&g.amsg[(ll)growl * H + (k - AF)]);
                }
                pv[t] = v;
            }
        }
    };
    auto cpB = [&](int c, int s) {
        const int kbase = c * 32 + half * 16;
        const uint dst = sb + (uint)s * BUFB + (uint)(row2 * 80 + half * 32);
        cp16(dst + 2 * PLNB,      wg_hi + kbase);
        cp16(dst + 2 * PLNB + 16, wg_hi + kbase + 8);
        cp16(dst + 3 * PLNB,      wg_lo + kbase);
        cp16(dst + 3 * PLNB + 16, wg_lo + kbase + 8);
    };
    auto stsA = [&](int s) {
        char* base = smem + (size_t)s * BUFB;
        uint ao = (uint)(row2 * 40 + half * 16);
#pragma unroll
        for (int i = 0; i < 4; i++) {
            uint2 hv = make_uint2(hi_pair(pv[4 * i], pv[4 * i + 1]),
                                  hi_pair(pv[4 * i + 2], pv[4 * i + 3]));
            uint2 lv = make_uint2(lo_pair(pv[4 * i], pv[4 * i + 1]),
                                  lo_pair(pv[4 * i + 2], pv[4 * i + 3]));
            *(uint2*)(base + ((ao + i * 4) << 1)) = hv;
            *(uint2*)(base + PLNB + ((ao + i * 4) << 1)) = lv;
        }
    };

    // prologue: fill buffer 0
    prefetchA(0);
    cpB(0, 0);
    cp_commit();
    stsA(0);
    cp_wait0();
    __syncthreads();

    for (int c = 0; c < KT; c++) {
        const int s = c & 1, ns = s ^ 1;
        if (c + 1 < KT) { prefetchA(c + 1); cpB(c + 1, ns); }
        cp_commit();

        // ---- compute chunk c from buffer s ----
        const uint bufo = sb + (uint)s * BUFB;
#pragma unroll
        for (int ks = 0; ks < 2; ks++) {
            const uint kb2 = (uint)(ks * 32);
            uint Ah[2][4], Al[2][4], Bh[4][4], Bl[4][4];
#pragma unroll
            for (int mi = 0; mi < 2; mi++) {
                ldsm4(Ah[mi], bufo + offA + kb2 + mi * 1280);
                ldsm4(Al[mi], bufo + offA + PLNB + kb2 + mi * 1280);
            }
#pragma unroll
            for (int nt = 0; nt < 4; nt++) {
                ldsm4(Bh[nt], bufo + offB + kb2 + nt * 1280);
                ldsm4(Bl[nt], bufo + offB + PLNB + kb2 + nt * 1280);
            }
#pragma unroll
            for (int mi = 0; mi < 2; mi++)
#pragma unroll
                for (int nt = 0; nt < 4; nt++)
#pragma unroll
                    for (int sub = 0; sub < 2; sub++) {
                        const int ni = nt * 2 + sub;
                        mma16816(acc[mi][ni], Ah[mi], &Bh[nt][sub * 2]);
                        mma16816(acc[mi][ni], Ah[mi], &Bl[nt][sub * 2]);
                        mma16816(acc[mi][ni], Al[mi], &Bh[nt][sub * 2]);
                    }
        }

        if (c + 1 < KT) stsA(ns);
        cp_wait0();
        __syncthreads();
    }

    // ---------------- epilogue ----------------
    const int grp = lane >> 2, qi = lane & 3;
#pragma unroll
    for (int mi = 0; mi < 2; mi++) {
        const int r0 = bm + wr * 32 + mi * 16 + grp;
        const int r1 = r0 + 8;
        float w0 = 0.f, w1 = 0.f;
        if (MODE == 2) {
            w0 = (r0 < g.M) ? __ldg(&g.w_atoms[r0]) : 0.f;
            w1 = (r1 < g.M) ? __ldg(&g.w_atoms[r1]) : 0.f;
        }
#pragma unroll
        for (int ni = 0; ni < 8; ni++) {
            const int col = bn + wc * 64 + ni * 8 + qi * 2;
            float c0 = acc[mi][ni][0], c1 = acc[mi][ni][1];
            float c2 = acc[mi][ni][2], c3 = acc[mi][ni][3];
            if (MODE == 0) {
                if (r0 < g.M) *(float2*)&g.inp_out[(ll)r0 * H + col] = make_float2(c0, c1);
                if (r1 < g.M) *(float2*)&g.inp_out[(ll)r1 * H + col] = make_float2(c2, c3);
            } else if (MODE == 1) {
                if (r0 < g.M) {
                    float2 iv = *(const float2*)&g.inp[(ll)r0 * H + col];
                    *(float2*)&g.msg_out[(ll)r0 * H + col] =
                        make_float2(fmaxf(c0 + iv.x, 0.f), fmaxf(c1 + iv.y, 0.f));
                }
                if (r1 < g.M) {
                    float2 iv = *(const float2*)&g.inp[(ll)r1 * H + col];
                    *(float2*)&g.msg_out[(ll)r1 * H + col] =
                        make_float2(fmaxf(c2 + iv.x, 0.f), fmaxf(c3 + iv.y, 0.f));
                }
            } else {
                float2 bo = *(const float2*)&g.b_o[col];
                if (r0 < g.M)
                    *(float2*)&g.msg_out[(ll)r0 * H + col] =
                        make_float2(fmaxf(c0 + bo.x, 0.f) * w0, fmaxf(c1 + bo.y, 0.f) * w0);
                if (r1 < g.M)
                    *(float2*)&g.msg_out[(ll)r1 * H + col] =
                        make_float2(fmaxf(c2 + bo.x, 0.f) * w1, fmaxf(c3 + bo.y, 0.f) * w1);
            }
        }
    }
}

// ---------------- weight prepack: [K x 256] fp32 -> [256 x Kpad] bf16 hi/lo ----
__global__ void prepack_w(const float* __restrict__ src, ushort* __restrict__ hi,
                          ushort* __restrict__ lo, int K, int Kpad) {
    int idx = blockIdx.x * 256 + threadIdx.x;
    if (idx >= 256 * Kpad) return;
    int n = idx / Kpad, k = idx - n * Kpad;
    float v = (k < K) ? src[(ll)k * 256 + n] : 0.f;
    uint u = __float_as_uint(v);
    hi[idx] = (ushort)(u >> 16);
    float lv = v - __uint_as_float(u & 0xFFFF0000u);
    __nv_bfloat16 b = __float2bfloat16(lv);
    lo[idx] = *(ushort*)&b;
}

// ---------------- small kernels ----------------
// relu applied on read (idempotent for already-relu'd buffers)
__global__ __launch_bounds__(256) void gather_kernel(const float* __restrict__ msg,
                                                     const float* __restrict__ w_bonds,
                                                     const int* __restrict__ a2b,
                                                     float* __restrict__ amsg) {
    int tid = threadIdx.x;
    int a = blockIdx.x * 4 + (tid >> 6);
    int lane = tid & 63;
    float4 s = make_float4(0.f, 0.f, 0.f, 0.f);
#pragma unroll
    for (int j = 0; j < MAXNB; j++) {
        int b = a2b[a * MAXNB + j];
        float w = w_bonds[b];
        float4 mv = *(const float4*)&msg[(ll)b * H + lane * 4];
        s.x += w * fmaxf(mv.x, 0.f); s.y += w * fmaxf(mv.y, 0.f);
        s.z += w * fmaxf(mv.z, 0.f); s.w += w * fmaxf(mv.w, 0.f);
    }
    *(float4*)&amsg[(ll)a * H + lane * 4] = s;
}

__global__ void zero_kernel(float* molsum, float* wsum) {
    int i = blockIdx.x * 256 + threadIdx.x;
    if (i < NM * H) molsum[i] = 0.f;
    if (i < NM) wsum[i] = 0.f;
}
__global__ void wsum_kernel(const float* __restrict__ w_atoms, const int* __restrict__ mol_ids,
                            float* __restrict__ wsum) {
    int i = blockIdx.x * 256 + threadIdx.x;
    if (i < NA) atomicAdd(&wsum[mol_ids[i]], w_atoms[i]);
}

__global__ __launch_bounds__(256) void segreduce_kernel(const float* __restrict__ hid,
                                                        const int* __restrict__ mol_ids,
                                                        float* __restrict__ molsum) {
    int col = blockIdx.y * 128 + (threadIdx.x & 127);
    int rbase = blockIdx.x * 128 + (threadIdx.x >> 7) * 64;
    if (rbase >= NA) return;
    int rend = rbase + 64; if (rend > NA) rend = NA;
    int cur = -1; float s = 0.f;
    for (int r = rbase; r < rend; r++) {
        int m = __ldg(&mol_ids[r]);
        float v = hid[(ll)r * H + col];
        if (m != cur) {
            if (cur >= 0) atomicAdd(&molsum[(ll)cur * H + col], s);
            cur = m; s = 0.f;
        }
        s += v;
    }
    if (cur >= 0) atomicAdd(&molsum[(ll)cur * H + col], s);
}

__global__ void finalize_kernel(const float* __restrict__ molsum, const float* __restrict__ wsum,
                                const float* __restrict__ deg, float* __restrict__ out) {
    int m = blockIdx.x, hc = threadIdx.x;
    float w = wsum[m];
    float v = (w > 0.f) ? molsum[m * H + hc] / w : 0.f;
    out[m * H + hc] = deg[m] * v;
}

extern "C" void kernel_launch(void* const* d_in, const int* in_sizes, int n_in,
                              void* d_out, int out_size) {
    const float* f_atoms = (const float*)d_in[0];
    const float* f_bonds = (const float*)d_in[1];
    const float* w_atoms = (const float*)d_in[2];
    const float* w_bonds = (const float*)d_in[3];
    const float* W_i = (const float*)d_in[4];
    const float* W_h = (const float*)d_in[5];
    const float* W_o = (const float*)d_in[6];
    const float* b_o = (const float*)d_in[7];
    const float* deg = (const float*)d_in[8];
    const int* a2b = (const int*)d_in[9];
    const int* b2a = (const int*)d_in[10];
    const int* b2revb = (const int*)d_in[11];
    const int* mol_ids = (const int*)d_in[12];

    float *p_inp, *p_msg0, *p_msg1, *p_amsg, *p_molsum, *p_wsum;
    ushort *p_wih, *p_wil, *p_whh, *p_whl, *p_woh, *p_wol;
    cudaGetSymbolAddress((void**)&p_inp, g_inp);
    cudaGetSymbolAddress((void**)&p_msg0, g_msg0);
    cudaGetSymbolAddress((void**)&p_msg1, g_msg1);
    cudaGetSymbolAddress((void**)&p_amsg, g_amsg);
    cudaGetSymbolAddress((void**)&p_molsum, g_molsum);
    cudaGetSymbolAddress((void**)&p_wsum, g_wsum);
    cudaGetSymbolAddress((void**)&p_wih, g_wi_hi);
    cudaGetSymbolAddress((void**)&p_wil, g_wi_lo);
    cudaGetSymbolAddress((void**)&p_whh, g_wh_hi);
    cudaGetSymbolAddress((void**)&p_whl, g_wh_lo);
    cudaGetSymbolAddress((void**)&p_woh, g_wo_hi);
    cudaGetSymbolAddress((void**)&p_wol, g_wo_lo);

    static int smem_set = 0;
    cudaFuncSetAttribute(hgemm<0>, cudaFuncAttributeMaxDynamicSharedMemorySize, SMEM_TOTAL);
    cudaFuncSetAttribute(hgemm<1>, cudaFuncAttributeMaxDynamicSharedMemorySize, SMEM_TOTAL);
    cudaFuncSetAttribute(hgemm<2>, cudaFuncAttributeMaxDynamicSharedMemorySize, SMEM_TOTAL);
    (void)smem_set;

    zero_kernel<<<NM, 256>>>(p_molsum, p_wsum);
    prepack_w<<<(256 * KP0 + 255) / 256, 256>>>(W_i, p_wih, p_wil, BF, KP0);
    prepack_w<<<(256 * KP1 + 255) / 256, 256>>>(W_h, p_whh, p_whl, H, KP1);
    prepack_w<<<(256 * KP2 + 255) / 256, 256>>>(W_o, p_woh, p_wol, AF + H, KP2);

    dim3 gb(MT_B, 2), ga(MT_A, 2);

    // input layer: inp = f_bonds @ W_i  (relu applied by readers)
    TArgs g0 = {};
    g0.A = f_bonds; g0.w_hi = p_wih; g0.w_lo = p_wil;
    g0.inp_out = p_inp; g0.M = NB;
    hgemm<0><<<gb, 256, SMEM_TOTAL>>>(g0);

    // depth iter 1 (sources: relu(inp) via relu-on-read)
    gather_kernel<<<NA / 4, 256>>>(p_inp, w_bonds, a2b, p_amsg);
    TArgs g1 = {};
    g1.w_hi = p_whh; g1.w_lo = p_whl; g1.amsg = p_amsg; g1.msgc = p_inp;
    g1.b2a = b2a; g1.b2revb = b2revb; g1.inp = p_inp; g1.msg_out = p_msg1; g1.M = NB;
    hgemm<1><<<gb, 256, SMEM_TOTAL>>>(g1);

    // depth iter 2
    gather_kernel<<<NA / 4, 256>>>(p_msg1, w_bonds, a2b, p_amsg);
    TArgs g2 = g1;
    g2.msgc = p_msg1; g2.msg_out = p_msg0;
    hgemm<1><<<gb, 256, SMEM_TOTAL>>>(g2);

    // readout
    gather_kernel<<<NA / 4, 256>>>(p_msg0, w_bonds, a2b, p_amsg);
    wsum_kernel<<<(NA + 255) / 256, 256>>>(w_atoms, mol_ids, p_wsum);

    // atom readout GEMM -> hidden*w rows into g_msg1 scratch
    TArgs g3 = {};
    g3.fatoms = f_atoms; g3.amsg = p_amsg; g3.w_hi = p_woh; g3.w_lo = p_wol;
    g3.b_o = b_o; g3.w_atoms = w_atoms; g3.msg_out = p_msg1; g3.M = NA;
    hgemm<2><<<ga, 256, SMEM_TOTAL>>>(g3);

    segreduce_kernel<<<dim3(MT_A, 2), 256>>>(p_msg1, mol_ids, p_molsum);
    finalize_kernel<<<NM, 256>>>(p_molsum, p_wsum, deg, (float*)d_out);
}